// round 3
// baseline (speedup 1.0000x reference)
#include <cuda_runtime.h>

typedef unsigned long long u64;
typedef unsigned int u32;

#define NTH 256
#define TILE_W 256
#define TILE_H 128
#define IMG 1024
#define NBATCH 32
#define STEPS (TILE_H + 10)
#define HALF_STRIDE 280           // u64 units; 2240 B == 64 mod 128 -> bank-disjoint halves
#define NPIX (32.0f * 1024.0f * 1024.0f)

__device__ float g_accum;
__global__ void k_zero() { g_accum = 0.0f; }

// Normalized 11-tap Gaussian, sigma=1.5
#define W0 0.00102838f
#define W1 0.00759878f
#define W2 0.03600077f
#define W3 0.10936072f
#define W4 0.21300560f
#define W5 0.26601180f

__device__ __forceinline__ u64 pack2(float lo, float hi) {
    u64 r;
    asm("mov.b64 %0, {%1,%2};" : "=l"(r) : "f"(lo), "f"(hi));
    return r;
}
__device__ __forceinline__ void unpack2(u64 v, float& lo, float& hi) {
    asm("mov.b64 {%0,%1}, %2;" : "=f"(lo), "=f"(hi) : "l"(v));
}
// d = a * b + c on packed f32x2 (sm_103a FFMA2, PTX-only)
__device__ __forceinline__ u64 ffma2(u64 a, u64 b, u64 c) {
    u64 d;
    asm("fma.rn.f32x2 %0, %1, %2, %3;" : "=l"(d) : "l"(a), "l"(b), "l"(c));
    return d;
}
__device__ __forceinline__ void lds2(u32 addr, u64& a, u64& b) {
    asm volatile("ld.shared.v2.u64 {%0,%1}, [%2];" : "=l"(a), "=l"(b) : "r"(addr));
}

__global__ __launch_bounds__(NTH, 2)
void k_ssim(const float* __restrict__ img1, const float* __restrict__ img2) {
    __shared__ __align__(16) u64 raw[2 * 2 * HALF_STRIDE];
    __shared__ float wpart[NTH / 32];

    u32 sbase;
    asm("{ .reg .u64 t; cvta.to.shared.u64 t, %1; cvt.u32.u64 %0, t; }"
        : "=r"(sbase) : "l"(raw));

    const int tid  = threadIdx.x;
    const int half = tid & 1;
    const int p    = tid >> 1;
    const int x0 = blockIdx.x * TILE_W;
    const int y0 = blockIdx.y * TILE_H;
    const size_t ofs = (size_t)blockIdx.z * (size_t)(IMG * IMG);
    const float* p1 = img1 + ofs;
    const float* p2 = img2 + ofs;

    const u64 GW[11] = {
        pack2(W0, W0), pack2(W1, W1), pack2(W2, W2), pack2(W3, W3), pack2(W4, W4),
        pack2(W5, W5),
        pack2(W4, W4), pack2(W3, W3), pack2(W2, W2), pack2(W1, W1), pack2(W0, W0)
    };

    const int c1 = tid;
    const int c2 = tid + NTH;
    const bool act2 = (c2 < TILE_W + 10);
    const int gx1 = x0 - 5 + c1;
    const int gx2 = x0 - 5 + c2;
    const bool okx1 = ((unsigned)gx1 < (unsigned)IMG);
    const bool okx2 = act2 && ((unsigned)gx2 < (unsigned)IMG);

    u64 ring0[11], ring1[11];
    float ssum = 0.0f;

    // depth-2 prefetch buffers, parity-indexed (compile-time after unroll)
    float pa1[2], pb1[2], pa2[2], pb2[2];
#pragma unroll
    for (int q = 0; q < 2; ++q) {       // preload rows 0 (parity 0) and 1 (parity 1)
        int ry = y0 - 5 + q;
        bool oky = ((unsigned)ry < (unsigned)IMG);
        const float* r1 = p1 + (size_t)ry * IMG;
        const float* r2 = p2 + (size_t)ry * IMG;
        pa1[q] = (oky && okx1) ? __ldg(r1 + gx1) : 0.0f;
        pb1[q] = (oky && okx1) ? __ldg(r2 + gx1) : 0.0f;
        pa2[q] = (oky && okx2) ? __ldg(r1 + gx2) : 0.0f;
        pb2[q] = (oky && okx2) ? __ldg(r2 + gx2) : 0.0f;
    }

    for (int ib = 0; ib < STEPS; ib += 22) {
#pragma unroll
        for (int m = 0; m < 22; ++m) {
            const int i = ib + m;
            if (i < STEPS) {                 // uniform across block
                const int buf = m & 1;       // compile-time (22 even)
                const int pq2 = m & 1;       // prefetch parity, compile-time
                // ---- stage row i from prefetch regs (loaded 2 iterations ago) ----
                {
                    float s = pa1[pq2] + pb1[pq2], d = pa1[pq2] - pb1[pq2];
                    raw[buf * (2 * HALF_STRIDE) + 0 * HALF_STRIDE + c1] = pack2(s, d);
                    raw[buf * (2 * HALF_STRIDE) + 1 * HALF_STRIDE + c1] = pack2(s * s, d * d);
                    if (act2) {
                        float s2 = pa2[pq2] + pb2[pq2], d2 = pa2[pq2] - pb2[pq2];
                        raw[buf * (2 * HALF_STRIDE) + 0 * HALF_STRIDE + c2] = pack2(s2, d2);
                        raw[buf * (2 * HALF_STRIDE) + 1 * HALF_STRIDE + c2] = pack2(s2 * s2, d2 * d2);
                    }
                }
                __syncthreads();
                // ---- issue loads for row i+2 into this parity's buffer ----
                {
                    int ry = y0 - 5 + i + 2;
                    bool oky = ((unsigned)ry < (unsigned)IMG) && (i + 2 < STEPS);
                    const float* r1 = p1 + (size_t)ry * IMG;
                    const float* r2 = p2 + (size_t)ry * IMG;
                    pa1[pq2] = (oky && okx1) ? __ldg(r1 + gx1) : 0.0f;
                    pb1[pq2] = (oky && okx1) ? __ldg(r2 + gx1) : 0.0f;
                    pa2[pq2] = (oky && okx2) ? __ldg(r1 + gx2) : 0.0f;
                    pb2[pq2] = (oky && okx2) ? __ldg(r2 + gx2) : 0.0f;
                }
                // ---- horizontal 11-tap conv, 2 columns ----
                u64 t[12];
                const u32 base = sbase + (u32)((buf * (2 * HALF_STRIDE) + half * HALF_STRIDE + 2 * p) * 8);
#pragma unroll
                for (int k = 0; k < 6; ++k)
                    lds2(base + k * 16u, t[2 * k], t[2 * k + 1]);
                u64 h0 = 0ull, h1 = 0ull;
#pragma unroll
                for (int u = 0; u < 11; ++u) {
                    h0 = ffma2(t[u],     GW[u], h0);
                    h1 = ffma2(t[u + 1], GW[u], h1);
                }
                ring0[m % 11] = h0;          // slot == i % 11 (ib multiple of 22)
                ring1[m % 11] = h1;

                // ---- vertical conv + SSIM when window full ----
                if (i >= 10) {
                    u64 v0 = 0ull, v1 = 0ull;
#pragma unroll
                    for (int j = 0; j < 11; ++j) {
                        const int s = (m + 1 + j) % 11;
                        v0 = ffma2(ring0[s], GW[j], v0);
                        v1 = ffma2(ring1[s], GW[j], v1);
                    }
                    u64 w0 = __shfl_xor_sync(0xffffffffu, v0, 1);
                    u64 w1 = __shfl_xor_sync(0xffffffffu, v1, 1);
                    u64 ab = half ? w1 : v0;
                    u64 pq = half ? v1 : w0;
                    float A, B, P, Q;
                    unpack2(ab, A, B);
                    unpack2(pq, P, Q);
                    float A2 = A * A, B2 = B * B;
                    float cross = 0.5f * (A2 - B2);
                    float sums  = 0.5f * (A2 + B2);
                    float t12   = 0.5f * (P - Q);
                    float tss   = 0.5f * (P + Q);
                    float num = (cross + 1e-4f) * (t12 - cross + 9e-4f);
                    float den = (sums  + 1e-4f) * (tss - sums  + 9e-4f);
                    ssum += __fdividef(num, den);
                }
            }
        }
    }

#pragma unroll
    for (int off = 16; off > 0; off >>= 1)
        ssum += __shfl_xor_sync(0xffffffffu, ssum, off);
    if ((tid & 31) == 0) wpart[tid >> 5] = ssum;
    __syncthreads();
    if (tid == 0) {
        float acc = 0.0f;
#pragma unroll
        for (int w = 0; w < NTH / 32; ++w) acc += wpart[w];
        atomicAdd(&g_accum, acc);
    }
}

__global__ void k_final(float* out) {
    out[0] = 1.0f - g_accum * (1.0f / NPIX);
}

extern "C" void kernel_launch(void* const* d_in, const int* in_sizes, int n_in,
                              void* d_out, int out_size) {
    const float* img1 = (const float*)d_in[0];
    const float* img2 = (const float*)d_in[1];
    float* out = (float*)d_out;

    k_zero<<<1, 1>>>();
    dim3 grid(IMG / TILE_W, IMG / TILE_H, NBATCH);
    k_ssim<<<grid, NTH>>>(img1, img2);
    k_final<<<1, 1>>>(out);
}